// round 14
// baseline (speedup 1.0000x reference)
#include <cuda_runtime.h>
#include <cuda_fp16.h>
#include <cstdint>

#define NROWS 4096
#define HDIM  512
#define VDIM  32000
#define SDIM  400
#define BDIM  32
#define CDIM  620
#define OUTW  32620          // VDIM + CDIM
#define BM    128
#define BN    128
#define BK    32
#define NSTAGE (HDIM / BK)   // 16
#define NTILES (VDIM / BN)   // 250
#define ATILEB 10240         // A tile bytes: 128 rows * 40 halves * 2
#define STAGEB 20480         // bytes per stage (A+B)
#define DYNSMEM (3 * STAGEB) // 61440 -> 2 CTA/SM easily
#define NCPEXT 512           // copyext pieces (8 t-rows each)

__device__ float  g_pcopy[NROWS];
__device__ float  g_partial[NROWS * NTILES];
__device__ __half g_hh[NROWS * HDIM];
__device__ __half g_Wh[(size_t)VDIM * HDIM];

// ---------------------------------------------------------------------------
__device__ __forceinline__ uint32_t smem_u32(const void* p) {
    return (uint32_t)__cvta_generic_to_shared(p);
}
__device__ __forceinline__ void cp_async16(uint32_t dst, const void* src) {
    asm volatile("cp.async.cg.shared.global [%0], [%1], 16;\n" :: "r"(dst), "l"(src));
}
__device__ __forceinline__ void cp_commit() { asm volatile("cp.async.commit_group;\n"); }
template<int N> __device__ __forceinline__ void cp_wait() {
    asm volatile("cp.async.wait_group %0;\n" :: "n"(N));
}
__device__ __forceinline__ void ldsm_x4(uint32_t& r0, uint32_t& r1,
                                        uint32_t& r2, uint32_t& r3, uint32_t a) {
    asm volatile("ldmatrix.sync.aligned.m8n8.x4.shared.b16 {%0,%1,%2,%3}, [%4];"
                 : "=r"(r0), "=r"(r1), "=r"(r2), "=r"(r3) : "r"(a));
}

__device__ __forceinline__ void mma_f16(float c[4], uint32_t a0, uint32_t a1,
                                        uint32_t a2, uint32_t a3,
                                        uint32_t b0, uint32_t b1) {
    asm volatile(
        "mma.sync.aligned.m16n8k16.row.col.f32.f16.f16.f32 "
        "{%0,%1,%2,%3}, {%4,%5,%6,%7}, {%8,%9}, {%0,%1,%2,%3};"
        : "+f"(c[0]), "+f"(c[1]), "+f"(c[2]), "+f"(c[3])
        : "r"(a0), "r"(a1), "r"(a2), "r"(a3), "r"(b0), "r"(b1));
}

#define LOADAB(A_, B_, kkb) do {                                             \
    _Pragma("unroll")                                                        \
    for (int mf_ = 0; mf_ < 4; mf_++)                                        \
        ldsm_x4(A_[mf_][0], A_[mf_][1], A_[mf_][2], A_[mf_][3],              \
                aaddr + (uint32_t)(mf_ * 1280 + (kkb)));                     \
    _Pragma("unroll")                                                        \
    for (int np_ = 0; np_ < 2; np_++)                                        \
        ldsm_x4(B_[2 * np_][0], B_[2 * np_][1],                              \
                B_[2 * np_ + 1][0], B_[2 * np_ + 1][1],                      \
                baddr + (uint32_t)(np_ * 1280 + (kkb)));                     \
} while (0)

#define MMAAB(A_, B_) do {                                                   \
    _Pragma("unroll")                                                        \
    for (int mf_ = 0; mf_ < 4; mf_++)                                        \
        _Pragma("unroll")                                                    \
        for (int nf_ = 0; nf_ < 4; nf_++)                                    \
            mma_f16(c[mf_][nf_], A_[mf_][0], A_[mf_][1], A_[mf_][2],         \
                    A_[mf_][3], B_[nf_][0], B_[nf_][1]);                     \
} while (0)

// ---------------------------------------------------------------------------
// conv: float -> half (rn), vectorized
// ---------------------------------------------------------------------------
__global__ void conv_kernel(const float4* __restrict__ src,
                            __half2* __restrict__ dst, int n4) {
    int idx = blockIdx.x * 256 + threadIdx.x;
    if (idx >= n4) return;
    float4 v = src[idx];
    dst[2 * idx]     = __floats2half2_rn(v.x, v.y);
    dst[2 * idx + 1] = __floats2half2_rn(v.z, v.w);
}

// ---------------------------------------------------------------------------
// K1: p_copy[n] = sigmoid(hidden[n] . Wc + bc)
// ---------------------------------------------------------------------------
__global__ void pcopy_kernel(const float* __restrict__ hidden,
                             const float* __restrict__ Wc,
                             const float* __restrict__ bc) {
    int warp = (blockIdx.x * blockDim.x + threadIdx.x) >> 5;
    int lane = threadIdx.x & 31;
    if (warp >= NROWS) return;
    const float* h = hidden + (size_t)warp * HDIM;
    float s = 0.f;
    #pragma unroll
    for (int k = lane; k < HDIM; k += 32) s += h[k] * Wc[k];
    #pragma unroll
    for (int o = 16; o > 0; o >>= 1) s += __shfl_down_sync(0xffffffffu, s, o);
    if (lane == 0) g_pcopy[warp] = 1.f / (1.f + __expf(-(s + bc[0])));
}

// ---------------------------------------------------------------------------
// K2 (fused launch): blocks [0, NCPEXT) do copy-ext; the rest do the f16
// mma.sync GEMM 128x128x512 with ldmatrix + 3-stage cp.async + exp epilogue.
// The two workloads are independent (disjoint out columns) and complementary
// (GEMM is tensor/latency-bound with idle DRAM & issue; copyext fills them).
// ---------------------------------------------------------------------------
__device__ __forceinline__ void load_stage(const __half* __restrict__ hh,
                                           const __half* __restrict__ Wh,
                                           int m0, int n0, int k0,
                                           uint32_t aAddr, uint32_t bAddr, int tid) {
    #pragma unroll
    for (int q = 0; q < 2; q++) {
        int f = tid + q * 256;
        int r = f >> 2, c16 = f & 3;             // 4 x 16B chunks per 64B row
        uint32_t so = (uint32_t)(r * 80 + c16 * 16);
        cp_async16(aAddr + so, hh + (size_t)(m0 + r) * HDIM + k0 + c16 * 8);
        cp_async16(bAddr + so, Wh + (size_t)(n0 + r) * HDIM + k0 + c16 * 8);
    }
}

__global__ __launch_bounds__(256, 2)
void gemm_kernel(const __half* __restrict__ hh,
                 const __half* __restrict__ Wh,
                 const float* __restrict__ bias,
                 const float* __restrict__ attn,
                 const float* __restrict__ srcmap,
                 float* __restrict__ out) {
    extern __shared__ __align__(16) float dyn[];
    const int tid = threadIdx.x;
    const int bid = blockIdx.x;

    // ---------------- copy-ext path ----------------
    if (bid < NCPEXT) {
        float* a_s = dyn;                        // [8][SDIM]
        int b  = bid & 31;
        int t0 = (bid >> 5) << 3;

        for (int i = tid; i < 8 * SDIM; i += 256) {
            int r = i / SDIM, s = i - r * SDIM;
            a_s[r * SDIM + s] = attn[(size_t)((t0 + r) * BDIM + b) * SDIM + s];
        }
        __syncthreads();

        #pragma unroll 1
        for (int chunk = 0; chunk < 3; chunk++) {
            int c = chunk * 256 + tid;
            if (c < CDIM) {
                float acc[8];
                #pragma unroll
                for (int r = 0; r < 8; r++) acc[r] = 0.f;
                #pragma unroll 8
                for (int s = 0; s < SDIM; s++) {
                    float sv = srcmap[(size_t)(s * BDIM + b) * CDIM + c];
                    #pragma unroll
                    for (int r = 0; r < 8; r++) acc[r] += a_s[r * SDIM + s] * sv;
                }
                #pragma unroll
                for (int r = 0; r < 8; r++) {
                    int n = (t0 + r) * BDIM + b;
                    out[(size_t)n * OUTW + VDIM + c] = acc[r] * g_pcopy[n];
                }
            }
        }
        return;
    }

    // ---------------- GEMM path ----------------
    __shared__ float bias_s[BN];
    __shared__ float rs_s[4][BM];

    const int id = bid - NCPEXT;
    const int m0 = (id & 31) * BM;               // M fast -> W reuse in L2
    const int n0 = (id >> 5) * BN;
    const int wid = tid >> 5, lane = tid & 31;
    const int wm = wid & 1;          // 2 warps along M (64 rows each)
    const int wn = wid >> 1;         // 4 warps along N (32 cols each)
    const int g = lane >> 2, t = lane & 3;

    if (tid < BN) bias_s[tid] = bias[n0 + tid];

    float c[4][4][4];
    #pragma unroll
    for (int mf = 0; mf < 4; mf++)
        #pragma unroll
        for (int nf = 0; nf < 4; nf++)
            #pragma unroll
            for (int i = 0; i < 4; i++) c[mf][nf][i] = 0.f;

    const uint32_t sbase = smem_u32(dyn);
    const uint32_t stA[3] = { sbase, sbase + STAGEB, sbase + 2 * STAGEB };

    // ldmatrix per-lane offsets
    const uint32_t aLane = (uint32_t)((lane & 15) * 80 + (lane >> 4) * 16);
    const uint32_t bLane = (uint32_t)(((lane & 7) + ((lane >> 4) & 1) * 8) * 80
                                      + ((lane >> 3) & 1) * 16);
    const uint32_t aoff = (uint32_t)(wm * 64 * 80) + aLane;
    const uint32_t boff = (uint32_t)(ATILEB + wn * 32 * 80) + bLane;

    load_stage(hh, Wh, m0, n0, 0, stA[0], stA[0] + ATILEB, tid); cp_commit();
    load_stage(hh, Wh, m0, n0, BK, stA[1], stA[1] + ATILEB, tid); cp_commit();

    #pragma unroll 1
    for (int s = 0; s < NSTAGE; s++) {
        const int p = s % 3;
        if (s + 1 < NSTAGE) cp_wait<1>(); else cp_wait<0>();
        __syncthreads();

        const uint32_t aaddr = stA[p] + aoff;
        const uint32_t baddr = stA[p] + boff;

        uint32_t a0[4][4], b0[4][2], a1[4][4], b1[4][2];
        LOADAB(a0, b0, 0);
        LOADAB(a1, b1, 32);          // k+16 halves = +32 bytes

        if (s + 2 < NSTAGE) {
            const int q = (s + 2) % 3;
            load_stage(hh, Wh, m0, n0, (s + 2) * BK, stA[q], stA[q] + ATILEB, tid);
            cp_commit();
        }

        MMAAB(a0, b0);
        MMAAB(a1, b1);
    }
    __syncthreads();

    // ---- epilogue: exp(+bias), row-sum partials, transposed coalesced stores
    float rs[4][2];
    #pragma unroll
    for (int mf = 0; mf < 4; mf++) { rs[mf][0] = 0.f; rs[mf][1] = 0.f; }

    #pragma unroll
    for (int mf = 0; mf < 4; mf++)
        #pragma unroll
        for (int nf = 0; nf < 4; nf++)
            #pragma unroll
            for (int i = 0; i < 4; i++) {
                int col = wn * 32 + nf * 8 + 2 * t + (i & 1);
                float e = __expf(c[mf][nf][i] + bias_s[col]);
                c[mf][nf][i] = e;
                rs[mf][i >> 1] += e;
            }

    #pragma unroll
    for (int mf = 0; mf < 4; mf++)
        #pragma unroll
        for (int h = 0; h < 2; h++) {
            float v = rs[mf][h];
            v += __shfl_xor_sync(0xffffffffu, v, 1);
            v += __shfl_xor_sync(0xffffffffu, v, 2);
            if (t == 0) rs_s[wn][wm * 64 + mf * 16 + g + h * 8] = v;
        }
    __syncthreads();
    if (tid < BM) {
        float pr = rs_s[0][tid] + rs_s[1][tid] + rs_s[2][tid] + rs_s[3][tid];
        g_partial[(size_t)(m0 + tid) * NTILES + (id >> 5)] = pr;
    }

    #pragma unroll 1
    for (int ch = 0; ch < 4; ch++) {
        if (wn == ch) {
            #pragma unroll
            for (int mf = 0; mf < 4; mf++)
                #pragma unroll
                for (int nf = 0; nf < 4; nf++)
                    #pragma unroll
                    for (int i = 0; i < 4; i++) {
                        int row = wm * 64 + mf * 16 + g + (i >> 1) * 8;
                        int col = nf * 8 + 2 * t + (i & 1);
                        dyn[col * 132 + row] = c[mf][nf][i];
                    }
        }
        __syncthreads();
        #pragma unroll
        for (int k = 0; k < 4; k++) {
            int f = tid + k * 256;
            int row = f >> 3, cg = f & 7;
            float4 v4;
            v4.x = dyn[(cg * 4 + 0) * 132 + row];
            v4.y = dyn[(cg * 4 + 1) * 132 + row];
            v4.z = dyn[(cg * 4 + 2) * 132 + row];
            v4.w = dyn[(cg * 4 + 3) * 132 + row];
            *reinterpret_cast<float4*>(
                &out[(size_t)(m0 + row) * OUTW + n0 + ch * 32 + cg * 4]) = v4;
        }
        __syncthreads();
    }
}

// ---------------------------------------------------------------------------
// K3: per-row reduce 250 partials (deterministic), scale V-range of out
// ---------------------------------------------------------------------------
__global__ void scale_kernel(float* __restrict__ out) {
    const int n = blockIdx.x;
    const int tid = threadIdx.x;
    __shared__ float red[256];
    red[tid] = (tid < NTILES) ? g_partial[(size_t)n * NTILES + tid] : 0.f;
    __syncthreads();
    #pragma unroll
    for (int o = 128; o > 0; o >>= 1) {
        if (tid < o) red[tid] += red[tid + o];
        __syncthreads();
    }
    const float sc = (1.f - g_pcopy[n]) / red[0];
    float4* row = reinterpret_cast<float4*>(out + (size_t)n * OUTW);
    for (int i = tid; i < VDIM / 4; i += 256) {
        float4 x = row[i];
        x.x *= sc; x.y *= sc; x.z *= sc; x.w *= sc;
        row[i] = x;
    }
}

// ---------------------------------------------------------------------------
extern "C" void kernel_launch(void* const* d_in, const int* in_sizes, int n_in,
                              void* d_out, int out_size) {
    const float* hidden = (const float*)d_in[0];   // (4096, 512)
    const float* attn   = (const float*)d_in[1];   // (4096, 400)
    const float* W      = (const float*)d_in[2];   // (32000, 512)
    const float* bias   = (const float*)d_in[3];   // (32000,)
    const float* Wc     = (const float*)d_in[4];   // (1, 512)
    const float* bc     = (const float*)d_in[5];   // (1,)
    const float* srcmap = (const float*)d_in[6];   // (400, 32, 620)
    float* out = (float*)d_out;                    // (4096, 32620)

    cudaFuncSetAttribute(gemm_kernel,
                         cudaFuncAttributeMaxDynamicSharedMemorySize, DYNSMEM);

    __half* hh; cudaGetSymbolAddress((void**)&hh, g_hh);
    __half* Wh; cudaGetSymbolAddress((void**)&Wh, g_Wh);

    // launch order keeps gemm 4th (ncu -s 5 -c 1 lands on our 4th launch)
    pcopy_kernel<<<NROWS / 8, 256>>>(hidden, Wc, bc);
    conv_kernel<<<(VDIM * HDIM / 4 + 255) / 256, 256>>>(
        (const float4*)W, (__half2*)Wh, VDIM * HDIM / 4);
    conv_kernel<<<(NROWS * HDIM / 4 + 255) / 256, 256>>>(
        (const float4*)hidden, (__half2*)hh, NROWS * HDIM / 4);

    gemm_kernel<<<NCPEXT + 32 * NTILES, 256, DYNSMEM>>>(
        hh, Wh, bias, attn, srcmap, out);

    scale_kernel<<<NROWS, 256>>>(out);
}

// round 15
// speedup vs baseline: 1.0086x; 1.0086x over previous
#include <cuda_runtime.h>
#include <cuda_fp16.h>
#include <cstdint>

#define NROWS 4096
#define HDIM  512
#define VDIM  32000
#define SDIM  400
#define BDIM  32
#define CDIM  620
#define OUTW  32620          // VDIM + CDIM
#define BM    128
#define BN    64
#define BK    32
#define NSTAGE (HDIM / BK)   // 16
#define NTILES (VDIM / BN)   // 500
#define ATILEB 10240         // A tile: 128 rows * 40 halves * 2
#define BTILEB 5120          // B tile: 64 rows * 40 halves * 2
#define STAGEB (ATILEB + BTILEB)     // 15360
#define DYNSMEM (3 * STAGEB)         // 46080 -> 4 CTA/SM (RF-capped)
#define NCPEXT 512           // copyext pieces (8 t-rows each)

__device__ float  g_pcopy[NROWS];
__device__ float  g_partial[NROWS * NTILES];
__device__ __half g_hh[NROWS * HDIM];
__device__ __half g_Wh[(size_t)VDIM * HDIM];

// ---------------------------------------------------------------------------
__device__ __forceinline__ uint32_t smem_u32(const void* p) {
    return (uint32_t)__cvta_generic_to_shared(p);
}
__device__ __forceinline__ void cp_async16(uint32_t dst, const void* src) {
    asm volatile("cp.async.cg.shared.global [%0], [%1], 16;\n" :: "r"(dst), "l"(src));
}
__device__ __forceinline__ void cp_commit() { asm volatile("cp.async.commit_group;\n"); }
template<int N> __device__ __forceinline__ void cp_wait() {
    asm volatile("cp.async.wait_group %0;\n" :: "n"(N));
}
__device__ __forceinline__ void ldsm_x4(uint32_t& r0, uint32_t& r1,
                                        uint32_t& r2, uint32_t& r3, uint32_t a) {
    asm volatile("ldmatrix.sync.aligned.m8n8.x4.shared.b16 {%0,%1,%2,%3}, [%4];"
                 : "=r"(r0), "=r"(r1), "=r"(r2), "=r"(r3) : "r"(a));
}

__device__ __forceinline__ void mma_f16(float c[4], uint32_t a0, uint32_t a1,
                                        uint32_t a2, uint32_t a3,
                                        uint32_t b0, uint32_t b1) {
    asm volatile(
        "mma.sync.aligned.m16n8k16.row.col.f32.f16.f16.f32 "
        "{%0,%1,%2,%3}, {%4,%5,%6,%7}, {%8,%9}, {%0,%1,%2,%3};"
        : "+f"(c[0]), "+f"(c[1]), "+f"(c[2]), "+f"(c[3])
        : "r"(a0), "r"(a1), "r"(a2), "r"(a3), "r"(b0), "r"(b1));
}

#define LOADAB(A_, B_, kkb) do {                                             \
    _Pragma("unroll")                                                        \
    for (int mf_ = 0; mf_ < 4; mf_++)                                        \
        ldsm_x4(A_[mf_][0], A_[mf_][1], A_[mf_][2], A_[mf_][3],              \
                aaddr + (uint32_t)(mf_ * 1280 + (kkb)));                     \
    _Pragma("unroll")                                                        \
    for (int np_ = 0; np_ < 2; np_++)                                        \
        ldsm_x4(B_[2 * np_][0], B_[2 * np_][1],                              \
                B_[2 * np_ + 1][0], B_[2 * np_ + 1][1],                      \
                baddr + (uint32_t)(np_ * 1280 + (kkb)));                     \
} while (0)

#define MMAAB(A_, B_) do {                                                   \
    _Pragma("unroll")                                                        \
    for (int mf_ = 0; mf_ < 4; mf_++)                                        \
        _Pragma("unroll")                                                    \
        for (int nf_ = 0; nf_ < 4; nf_++)                                    \
            mma_f16(c[mf_][nf_], A_[mf_][0], A_[mf_][1], A_[mf_][2],         \
                    A_[mf_][3], B_[nf_][0], B_[nf_][1]);                     \
} while (0)

// ---------------------------------------------------------------------------
// conv: float -> half (rn), vectorized
// ---------------------------------------------------------------------------
__global__ void conv_kernel(const float4* __restrict__ src,
                            __half2* __restrict__ dst, int n4) {
    int idx = blockIdx.x * 256 + threadIdx.x;
    if (idx >= n4) return;
    float4 v = src[idx];
    dst[2 * idx]     = __floats2half2_rn(v.x, v.y);
    dst[2 * idx + 1] = __floats2half2_rn(v.z, v.w);
}

// ---------------------------------------------------------------------------
// K1: p_copy[n] = sigmoid(hidden[n] . Wc + bc)
// ---------------------------------------------------------------------------
__global__ void pcopy_kernel(const float* __restrict__ hidden,
                             const float* __restrict__ Wc,
                             const float* __restrict__ bc) {
    int warp = (blockIdx.x * blockDim.x + threadIdx.x) >> 5;
    int lane = threadIdx.x & 31;
    if (warp >= NROWS) return;
    const float* h = hidden + (size_t)warp * HDIM;
    float s = 0.f;
    #pragma unroll
    for (int k = lane; k < HDIM; k += 32) s += h[k] * Wc[k];
    #pragma unroll
    for (int o = 16; o > 0; o >>= 1) s += __shfl_down_sync(0xffffffffu, s, o);
    if (lane == 0) g_pcopy[warp] = 1.f / (1.f + __expf(-(s + bc[0])));
}

// ---------------------------------------------------------------------------
// K2 (fused launch): blocks [0, NCPEXT) do copy-ext; the rest do the f16
// GEMM. CTA = 128 threads / 4 warps, tile 128x64 -> 4 independent CTAs per
// SM (4 barrier domains; a CTA at its barrier is covered by 3 others).
// ---------------------------------------------------------------------------
__device__ __forceinline__ void load_stage(const __half* __restrict__ hh,
                                           const __half* __restrict__ Wh,
                                           int m0, int n0, int k0,
                                           uint32_t aAddr, uint32_t bAddr, int tid) {
    #pragma unroll
    for (int q = 0; q < 4; q++) {                // A: 512 16B chunks
        int f = tid + q * 128;
        int r = f >> 2, c16 = f & 3;
        cp_async16(aAddr + (uint32_t)(r * 80 + c16 * 16),
                   hh + (size_t)(m0 + r) * HDIM + k0 + c16 * 8);
    }
    #pragma unroll
    for (int q = 0; q < 2; q++) {                // B: 256 16B chunks
        int f = tid + q * 128;
        int r = f >> 2, c16 = f & 3;
        cp_async16(bAddr + (uint32_t)(r * 80 + c16 * 16),
                   Wh + (size_t)(n0 + r) * HDIM + k0 + c16 * 8);
    }
}

__global__ __launch_bounds__(128, 4)
void gemm_kernel(const __half* __restrict__ hh,
                 const __half* __restrict__ Wh,
                 const float* __restrict__ bias,
                 const float* __restrict__ attn,
                 const float* __restrict__ srcmap,
                 float* __restrict__ out) {
    extern __shared__ __align__(16) float dyn[];
    const int tid = threadIdx.x;
    const int bid = blockIdx.x;

    // ---------------- copy-ext path ----------------
    if (bid < NCPEXT) {
        float* a_s = dyn;                        // [8][SDIM]
        int b  = bid & 31;
        int t0 = (bid >> 5) << 3;

        for (int i = tid; i < 8 * SDIM; i += 128) {
            int r = i / SDIM, s = i - r * SDIM;
            a_s[r * SDIM + s] = attn[(size_t)((t0 + r) * BDIM + b) * SDIM + s];
        }
        __syncthreads();

        #pragma unroll 1
        for (int chunk = 0; chunk < 5; chunk++) {
            int c = chunk * 128 + tid;
            if (c < CDIM) {
                float acc[8];
                #pragma unroll
                for (int r = 0; r < 8; r++) acc[r] = 0.f;
                #pragma unroll 8
                for (int s = 0; s < SDIM; s++) {
                    float sv = srcmap[(size_t)(s * BDIM + b) * CDIM + c];
                    #pragma unroll
                    for (int r = 0; r < 8; r++) acc[r] += a_s[r * SDIM + s] * sv;
                }
                #pragma unroll
                for (int r = 0; r < 8; r++) {
                    int n = (t0 + r) * BDIM + b;
                    out[(size_t)n * OUTW + VDIM + c] = acc[r] * g_pcopy[n];
                }
            }
        }
        return;
    }

    // ---------------- GEMM path ----------------
    __shared__ float bias_s[BN];
    __shared__ float rs_s[2][BM];

    const int id = bid - NCPEXT;
    const int m0 = (id & 31) * BM;               // M fast -> W reuse in L2
    const int nt = id >> 5;                      // n-tile index (0..499)
    const int n0 = nt * BN;
    const int wid = tid >> 5, lane = tid & 31;
    const int wm = wid & 1;          // 2 warps along M (64 rows each)
    const int wn = wid >> 1;         // 2 warps along N (32 cols each)
    const int g = lane >> 2, t = lane & 3;

    if (tid < BN) bias_s[tid] = bias[n0 + tid];

    float c[4][4][4];
    #pragma unroll
    for (int mf = 0; mf < 4; mf++)
        #pragma unroll
        for (int nf = 0; nf < 4; nf++)
            #pragma unroll
            for (int i = 0; i < 4; i++) c[mf][nf][i] = 0.f;

    const uint32_t sbase = smem_u32(dyn);
    const uint32_t stA[3] = { sbase, sbase + STAGEB, sbase + 2 * STAGEB };

    // ldmatrix per-lane offsets
    const uint32_t aLane = (uint32_t)((lane & 15) * 80 + (lane >> 4) * 16);
    const uint32_t bLane = (uint32_t)(((lane & 7) + ((lane >> 4) & 1) * 8) * 80
                                      + ((lane >> 3) & 1) * 16);
    const uint32_t aoff = (uint32_t)(wm * 64 * 80) + aLane;
    const uint32_t boff = (uint32_t)(ATILEB + wn * 32 * 80) + bLane;

    load_stage(hh, Wh, m0, n0, 0, stA[0], stA[0] + ATILEB, tid); cp_commit();
    load_stage(hh, Wh, m0, n0, BK, stA[1], stA[1] + ATILEB, tid); cp_commit();

    #pragma unroll 1
    for (int s = 0; s < NSTAGE; s++) {
        const int p = s % 3;
        if (s + 1 < NSTAGE) cp_wait<1>(); else cp_wait<0>();
        __syncthreads();

        const uint32_t aaddr = stA[p] + aoff;
        const uint32_t baddr = stA[p] + boff;

        uint32_t a0[4][4], b0[4][2], a1[4][4], b1[4][2];
        LOADAB(a0, b0, 0);
        LOADAB(a1, b1, 32);          // k+16 halves = +32 bytes

        if (s + 2 < NSTAGE) {
            const int q = (s + 2) % 3;
            load_stage(hh, Wh, m0, n0, (s + 2) * BK, stA[q], stA[q] + ATILEB, tid);
            cp_commit();
        }

        MMAAB(a0, b0);
        MMAAB(a1, b1);
    }
    __syncthreads();

    // ---- epilogue: exp(+bias), row-sum partials, transposed coalesced stores
    float rs[4][2];
    #pragma unroll
    for (int mf = 0; mf < 4; mf++) { rs[mf][0] = 0.f; rs[mf][1] = 0.f; }

    #pragma unroll
    for (int mf = 0; mf < 4; mf++)
        #pragma unroll
        for (int nf = 0; nf < 4; nf++)
            #pragma unroll
            for (int i = 0; i < 4; i++) {
                int col = wn * 32 + nf * 8 + 2 * t + (i & 1);
                float e = __expf(c[mf][nf][i] + bias_s[col]);
                c[mf][nf][i] = e;
                rs[mf][i >> 1] += e;
            }

    #pragma unroll
    for (int mf = 0; mf < 4; mf++)
        #pragma unroll
        for (int h = 0; h < 2; h++) {
            float v = rs[mf][h];
            v += __shfl_xor_sync(0xffffffffu, v, 1);
            v += __shfl_xor_sync(0xffffffffu, v, 2);
            if (t == 0) rs_s[wn][wm * 64 + mf * 16 + g + h * 8] = v;
        }
    __syncthreads();
    if (tid < BM) {
        float pr = rs_s[0][tid] + rs_s[1][tid];
        g_partial[(size_t)(m0 + tid) * NTILES + nt] = pr;
    }

    // 2 chunks of 32 cols: STS (conflict-free, stride 132) then float4 STG
    #pragma unroll 1
    for (int ch = 0; ch < 2; ch++) {
        if (wn == ch) {
            #pragma unroll
            for (int mf = 0; mf < 4; mf++)
                #pragma unroll
                for (int nf = 0; nf < 4; nf++)
                    #pragma unroll
                    for (int i = 0; i < 4; i++) {
                        int row = wm * 64 + mf * 16 + g + (i >> 1) * 8;
                        int col = nf * 8 + 2 * t + (i & 1);
                        dyn[col * 132 + row] = c[mf][nf][i];
                    }
        }
        __syncthreads();
        #pragma unroll
        for (int k = 0; k < 8; k++) {
            int f = tid + k * 128;
            int row = f >> 3, cg = f & 7;
            float4 v4;
            v4.x = dyn[(cg * 4 + 0) * 132 + row];
            v4.y = dyn[(cg * 4 + 1) * 132 + row];
            v4.z = dyn[(cg * 4 + 2) * 132 + row];
            v4.w = dyn[(cg * 4 + 3) * 132 + row];
            *reinterpret_cast<float4*>(
                &out[(size_t)(m0 + row) * OUTW + n0 + ch * 32 + cg * 4]) = v4;
        }
        __syncthreads();
    }
}

// ---------------------------------------------------------------------------
// K3: per-row reduce 500 partials (deterministic), scale V-range of out
// ---------------------------------------------------------------------------
__global__ void scale_kernel(float* __restrict__ out) {
    const int n = blockIdx.x;
    const int tid = threadIdx.x;
    __shared__ float red[512];
    red[tid] = (tid < NTILES) ? g_partial[(size_t)n * NTILES + tid] : 0.f;
    __syncthreads();
    #pragma unroll
    for (int o = 256; o > 0; o >>= 1) {
        if (tid < o) red[tid] += red[tid + o];
        __syncthreads();
    }
    const float sc = (1.f - g_pcopy[n]) / red[0];
    float4* row = reinterpret_cast<float4*>(out + (size_t)n * OUTW);
    for (int i = tid; i < VDIM / 4; i += 512) {
        float4 x = row[i];
        x.x *= sc; x.y *= sc; x.z *= sc; x.w *= sc;
        row[i] = x;
    }
}

// ---------------------------------------------------------------------------
extern "C" void kernel_launch(void* const* d_in, const int* in_sizes, int n_in,
                              void* d_out, int out_size) {
    const float* hidden = (const float*)d_in[0];   // (4096, 512)
    const float* attn   = (const float*)d_in[1];   // (4096, 400)
    const float* W      = (const float*)d_in[2];   // (32000, 512)
    const float* bias   = (const float*)d_in[3];   // (32000,)
    const float* Wc     = (const float*)d_in[4];   // (1, 512)
    const float* bc     = (const float*)d_in[5];   // (1,)
    const float* srcmap = (const float*)d_in[6];   // (400, 32, 620)
    float* out = (float*)d_out;                    // (4096, 32620)

    cudaFuncSetAttribute(gemm_kernel,
                         cudaFuncAttributeMaxDynamicSharedMemorySize, DYNSMEM);

    __half* hh; cudaGetSymbolAddress((void**)&hh, g_hh);
    __half* Wh; cudaGetSymbolAddress((void**)&Wh, g_Wh);

    // launch order keeps gemm 4th (ncu -s 5 -c 1 lands on our 4th launch)
    pcopy_kernel<<<NROWS / 8, 256>>>(hidden, Wc, bc);
    conv_kernel<<<(VDIM * HDIM / 4 + 255) / 256, 256>>>(
        (const float4*)W, (__half2*)Wh, VDIM * HDIM / 4);
    conv_kernel<<<(NROWS * HDIM / 4 + 255) / 256, 256>>>(
        (const float4*)hidden, (__half2*)hh, NROWS * HDIM / 4);

    gemm_kernel<<<NCPEXT + 32 * NTILES, 128, DYNSMEM>>>(
        hh, Wh, bias, attn, srcmap, out);

    scale_kernel<<<NROWS, 512>>>(out);
}